// round 2
// baseline (speedup 1.0000x reference)
#include <cuda_runtime.h>
#include <cuda_fp16.h>

#define Nn   1024
#define Cc   64
#define HID  128
#define TILE 32
#define NT   (Nn / TILE)              // 32
#define NPAIRS (NT * (NT + 1) / 2)    // 528
#define HCH  64

__device__ float g_pi[HID * Nn];
__device__ float g_pj[HID * Nn];

__device__ __forceinline__ __half2 tanh2(__half2 x) {
    unsigned xi = *(unsigned*)&x, yi;
    asm("tanh.approx.f16x2 %0, %1;" : "=r"(yi) : "r"(xi));
    return *(__half2*)&yi;
}

// ---------------------------------------------------------------------------
// Pre-pass (fp32, precise): pi[h,n] = sum_c W1[h,C+c]*tanh(x[c,n]) + b1[h]
//                           pj[h,n] = sum_c W1[h,  c]*tanh(x[c,n])
// ---------------------------------------------------------------------------
#define NCH 8
__global__ void prep_kernel(const float* __restrict__ x,
                            const float* __restrict__ W1,
                            const float* __restrict__ b1) {
    __shared__ float t_s[Cc][NCH];
    const int n0  = blockIdx.x * NCH;
    const int tid = threadIdx.x;

    for (int k = tid; k < Cc * NCH; k += 128) {
        int c = k / NCH, n = k % NCH;
        t_s[c][n] = tanhf(x[c * Nn + n0 + n]);
    }
    __syncthreads();

    const int h = tid;
    float accj[NCH], acci[NCH];
    const float bb = b1[h];
#pragma unroll
    for (int n = 0; n < NCH; n++) { accj[n] = 0.0f; acci[n] = bb; }

#pragma unroll
    for (int c = 0; c < Cc; c++) {
        float wj = W1[h * (2 * Cc) + c];
        float wi = W1[h * (2 * Cc) + Cc + c];
#pragma unroll
        for (int n = 0; n < NCH; n++) {
            float t = t_s[c][n];
            accj[n] = fmaf(wj, t, accj[n]);
            acci[n] = fmaf(wi, t, acci[n]);
        }
    }
#pragma unroll
    for (int n = 0; n < NCH; n++) {
        g_pj[h * Nn + n0 + n] = accj[n];
        g_pi[h * Nn + n0 + n] = acci[n];
    }
}

// ---------------------------------------------------------------------------
// Main pass, f16x2 tanh: per tile pair (ti<=tj) compute
//   e[i,j] = sum_h w2[h]*tanh(pi[h,i]+pj[h,j]),  e[j,i] likewise,
//   out[i,j] = out[j,i] = e[i,j]+e[j,i]+2*b2
// Thread -> il = tid>>3 (one i row), 4 consecutive j as 2 half2.
// half2 accumulators flushed to fp32 every 2 h-steps (accuracy).
// ---------------------------------------------------------------------------
__global__ void pair_kernel(const float* __restrict__ W2,
                            const float* __restrict__ b2,
                            float* __restrict__ out) {
    __shared__ __align__(16) __half2 pjJ2[HCH][TILE / 2];  // pj[h, j-pairs]
    __shared__ __align__(16) __half2 piJ2[HCH][TILE / 2];  // pi[h, j-pairs]
    __shared__ __align__(16) __half2 aeS[HCH][TILE];       // dup(pi[h,i])
    __shared__ __align__(16) __half2 atS[HCH][TILE];       // dup(pj[h,i])
    __shared__ __half2 w2s[HID];

    // triangular pair decode
    int rem = blockIdx.x, ti = 0, rowlen = NT;
    while (rem >= rowlen) { rem -= rowlen; ti++; rowlen--; }
    const int tj = ti + rem;
    const int i0 = ti * TILE, j0 = tj * TILE;

    const int tid = threadIdx.x;
    if (tid < HID) { float w = W2[tid]; w2s[tid] = __floats2half2_rn(w, w); }

    const int il = tid >> 3;           // 0..31
    const int jh = (tid & 7) * 2;      // half2 index: j = jh*2 .. jh*2+3

    float accf[8];
#pragma unroll
    for (int q = 0; q < 8; q++) accf[q] = 0.0f;

    for (int hc = 0; hc < HID / HCH; hc++) {
        __syncthreads();
        // stage chunk: convert fp32 globals -> half2 tiles
        for (int k = tid; k < HCH * TILE / 4; k += 256) {
            int hl = k >> 3;
            int q  = (k & 7) * 4;
            int hg = hc * HCH + hl;
            float4 vj = *(const float4*)&g_pj[hg * Nn + j0 + q];
            float4 vi = *(const float4*)&g_pi[hg * Nn + j0 + q];
            pjJ2[hl][q / 2]     = __floats2half2_rn(vj.x, vj.y);
            pjJ2[hl][q / 2 + 1] = __floats2half2_rn(vj.z, vj.w);
            piJ2[hl][q / 2]     = __floats2half2_rn(vi.x, vi.y);
            piJ2[hl][q / 2 + 1] = __floats2half2_rn(vi.z, vi.w);
            float4 ai = *(const float4*)&g_pi[hg * Nn + i0 + q];
            float4 aj = *(const float4*)&g_pj[hg * Nn + i0 + q];
            aeS[hl][q + 0] = __floats2half2_rn(ai.x, ai.x);
            aeS[hl][q + 1] = __floats2half2_rn(ai.y, ai.y);
            aeS[hl][q + 2] = __floats2half2_rn(ai.z, ai.z);
            aeS[hl][q + 3] = __floats2half2_rn(ai.w, ai.w);
            atS[hl][q + 0] = __floats2half2_rn(aj.x, aj.x);
            atS[hl][q + 1] = __floats2half2_rn(aj.y, aj.y);
            atS[hl][q + 2] = __floats2half2_rn(aj.z, aj.z);
            atS[hl][q + 3] = __floats2half2_rn(aj.w, aj.w);
        }
        __syncthreads();

#pragma unroll 4
        for (int hl2 = 0; hl2 < HCH / 2; hl2++) {
            __half2 a0 = __floats2half2_rn(0.f, 0.f);
            __half2 a1 = a0, a2 = a0, a3 = a0;
#pragma unroll
            for (int s = 0; s < 2; s++) {
                int hl = hl2 * 2 + s;
                __half2 w2  = w2s[hc * HCH + hl];
                __half2 ae  = aeS[hl][il];
                __half2 at  = atS[hl][il];
                __half2 bj0 = pjJ2[hl][jh + 0];
                __half2 bj1 = pjJ2[hl][jh + 1];
                __half2 bi0 = piJ2[hl][jh + 0];
                __half2 bi1 = piJ2[hl][jh + 1];

                __half2 e0 = tanh2(__hadd2(ae, bj0));
                __half2 e1 = tanh2(__hadd2(ae, bj1));
                __half2 t0 = tanh2(__hadd2(bi0, at));
                __half2 t1 = tanh2(__hadd2(bi1, at));

                a0 = __hfma2(w2, e0, a0);
                a1 = __hfma2(w2, e1, a1);
                a2 = __hfma2(w2, t0, a2);
                a3 = __hfma2(w2, t1, a3);
            }
            // flush to fp32 every 2 h-steps
            accf[0] += __low2float(a0);  accf[1] += __high2float(a0);
            accf[2] += __low2float(a1);  accf[3] += __high2float(a1);
            accf[4] += __low2float(a2);  accf[5] += __high2float(a2);
            accf[6] += __low2float(a3);  accf[7] += __high2float(a3);
        }
    }

    const float bb2 = 2.0f * b2[0];
    const int gi = i0 + il;
    const int jl = jh * 2;
    float4 o;
    o.x = accf[0] + accf[4] + bb2;
    o.y = accf[1] + accf[5] + bb2;
    o.z = accf[2] + accf[6] + bb2;
    o.w = accf[3] + accf[7] + bb2;

    *(float4*)&out[gi * Nn + j0 + jl] = o;       // upper tile, coalesced
    out[(j0 + jl + 0) * Nn + gi] = o.x;          // mirrored lower tile
    out[(j0 + jl + 1) * Nn + gi] = o.y;
    out[(j0 + jl + 2) * Nn + gi] = o.z;
    out[(j0 + jl + 3) * Nn + gi] = o.w;
}

extern "C" void kernel_launch(void* const* d_in, const int* in_sizes, int n_in,
                              void* d_out, int out_size) {
    const float* x  = (const float*)d_in[0];
    const float* W1 = (const float*)d_in[1];
    const float* b1 = (const float*)d_in[2];
    const float* W2 = (const float*)d_in[3];
    const float* b2 = (const float*)d_in[4];
    float* out = (float*)d_out;

    prep_kernel<<<Nn / NCH, 128>>>(x, W1, b1);
    pair_kernel<<<NPAIRS, 256>>>(W2, b2, out);
}

// round 3
// speedup vs baseline: 1.7627x; 1.7627x over previous
#include <cuda_runtime.h>

#define Nn   1024
#define Cc   64
#define HID  128
#define TS   16                         // output sub-tile edge
#define NTS  (Nn / TS)                  // 64
#define NUNITS (NTS * (NTS + 1) / 2)    // 2080

// interleaved: g_p[h*Nn + n] = (pi[h,n], pj[h,n])
__device__ float2 g_p[HID * Nn];

__device__ __forceinline__ float tanh_apx(float x) {
    float y;
    asm("tanh.approx.f32 %0, %1;" : "=f"(y) : "f"(x));
    return y;
}

// ---------------------------------------------------------------------------
// prep: pi[h,n] = sum_c W1[h,Cc+c]*tanh(x[c,n]) + b1[h]
//       pj[h,n] = sum_c W1[h,   c]*tanh(x[c,n])
// grid 128 blocks x 128 threads, each block an 8-column n chunk
// ---------------------------------------------------------------------------
#define NCH 8
__global__ void prep_kernel(const float* __restrict__ x,
                            const float* __restrict__ W1,
                            const float* __restrict__ b1) {
    __shared__ float t_s[Cc][NCH];
    const int n0  = blockIdx.x * NCH;
    const int tid = threadIdx.x;

    for (int k = tid; k < Cc * NCH; k += 128) {
        int c = k / NCH, n = k % NCH;
        t_s[c][n] = tanhf(x[c * Nn + n0 + n]);   // precise tanh in pre-pass
    }
    __syncthreads();

    const int h = tid;
    float accj[NCH], acci[NCH];
    const float bb = b1[h];
#pragma unroll
    for (int n = 0; n < NCH; n++) { accj[n] = 0.0f; acci[n] = bb; }

#pragma unroll
    for (int c = 0; c < Cc; c++) {
        float wj = W1[h * (2 * Cc) + c];
        float wi = W1[h * (2 * Cc) + Cc + c];
#pragma unroll
        for (int n = 0; n < NCH; n++) {
            float t = t_s[c][n];
            accj[n] = fmaf(wj, t, accj[n]);
            acci[n] = fmaf(wi, t, acci[n]);
        }
    }
#pragma unroll
    for (int n = 0; n < NCH; n++)
        g_p[h * Nn + n0 + n] = make_float2(acci[n], accj[n]);
}

// ---------------------------------------------------------------------------
// pair: triangular unit (a <= b) covers i-range [16a,16a+16), j-range
// [16b,16b+16). Each of the 256 threads owns one (i,j):
//   v = sum_h w2[h]*(tanh(pi_i + pj_j) + tanh(pi_j + pj_i)) + 2*b2
// writes out[i,j] and out[j,i] (diagonal units double-write same value).
// ---------------------------------------------------------------------------
__global__ __launch_bounds__(256) void pair_kernel(const float* __restrict__ W2,
                                                   const float* __restrict__ b2,
                                                   float* __restrict__ out) {
    __shared__ __align__(16) float2 pS[HID][2 * TS];   // [h][0..15]=i cols, [16..31]=j cols
    __shared__ float w2s[HID];

    // triangular decode
    int rem = blockIdx.x, a = 0, len = NTS;
    while (rem >= len) { rem -= len; a++; len--; }
    const int b  = a + rem;
    const int i0 = a * TS, j0 = b * TS;

    const int tid = threadIdx.x;
    if (tid < HID) w2s[tid] = W2[tid];

    // stage: 128 h x (16 i-cols + 16 j-cols) float2, as float4 (2 float2 each)
    // 16 float4 per h -> 2048 total -> 8 per thread
    for (int t = tid; t < HID * 16; t += 256) {
        int h    = t >> 4;
        int q    = t & 15;
        int side = q >> 3;            // 0 = i-side, 1 = j-side
        int c    = (q & 7) * 2;       // float2 column offset
        int src  = side ? j0 : i0;
        float4 v = *(const float4*)&g_p[h * Nn + src + c];
        *(float4*)&pS[h][side * TS + c] = v;
    }
    __syncthreads();

    const int ii = tid >> 4;      // 0..15
    const int jj = tid & 15;      // 0..15

    float acc1 = 0.0f, acc2 = 0.0f;
#pragma unroll 8
    for (int h = 0; h < HID; h++) {
        float2 ai = pS[h][ii];          // (pi_i, pj_i)
        float2 aj = pS[h][TS + jj];     // (pi_j, pj_j)
        float  w  = w2s[h];
        acc1 = fmaf(w, tanh_apx(ai.x + aj.y), acc1);   // e[i,j]
        acc2 = fmaf(w, tanh_apx(aj.x + ai.y), acc2);   // e[j,i]
    }

    const float v  = acc1 + acc2 + 2.0f * b2[0];
    const int gi = i0 + ii, gj = j0 + jj;
    out[gi * Nn + gj] = v;
    out[gj * Nn + gi] = v;     // mirror (same value by construction)
}

extern "C" void kernel_launch(void* const* d_in, const int* in_sizes, int n_in,
                              void* d_out, int out_size) {
    const float* x  = (const float*)d_in[0];
    const float* W1 = (const float*)d_in[1];
    const float* b1 = (const float*)d_in[2];
    const float* W2 = (const float*)d_in[3];
    const float* b2 = (const float*)d_in[4];
    float* out = (float*)d_out;

    prep_kernel<<<Nn / NCH, 128>>>(x, W1, b1);
    pair_kernel<<<NUNITS, 256>>>(W2, b2, out);
}